// round 13
// baseline (speedup 1.0000x reference)
#include <cuda_runtime.h>

#define KK    27
#define CH    64
#define CAPK  65536          // per-k entry capacity (expected ~6K)
#define EXT2  0.75f          // KP_EXTENT^2
#define INV_EXT 1.15470053837925f
#define TH2   (1.8675f * 1.8675f)
#define SLICES 22
#define PAD   68             // floats per xs row (272B, 16B-aligned)
#define CNT_STRIDE 64        // 256B between counters -> distinct L2 slices
#define WROWS 16             // rows per warp per tile (8 warps x 16 = 128)
#define BCTAS 296            // build CTAs (grid-stride over queries)
#define BCAP  2048           // per-CTA entry staging capacity (expected ~510)

// global scratch (static __device__, zero-initialized at module load)
__device__ unsigned g_pack[KK * CAPK];   // q<<16 | ind
__device__ float    g_w[KK * CAPK];
__device__ int      g_cnt[KK * CNT_STRIDE];
__device__ int      g_done;              // gemm exit counter (self-resetting)

// ---------------- packed f32x2 helpers -------------------------------------
#define PACK2(d, lo, hi) \
    asm("mov.b64 %0, {%1, %2};" : "=l"(d) : "r"(__float_as_uint(lo)), "r"(__float_as_uint(hi)))
#define FMA2(acc, a, b) \
    asm("fma.rn.f32x2 %0, %1, %2, %0;" : "+l"(acc) : "l"(a), "l"(b))
#define UNPACK2(lo, hi, v) \
    asm("mov.b64 {%0, %1}, %2;" : "=r"(lo), "=r"(hi) : "l"(v))

__device__ __forceinline__ void red_add_v4(float* p, float a, float b,
                                           float c, float d) {
    asm volatile("red.global.add.v4.f32 [%0], {%1, %2, %3, %4};"
                 :: "l"(p), "f"(a), "f"(b), "f"(c), "f"(d) : "memory");
}

__device__ __forceinline__ void cp8(float* dst_smem, const float* src) {
    unsigned d = (unsigned)__cvta_generic_to_shared(dst_smem);
    asm volatile("cp.async.ca.shared.global [%0], [%1], 8;"
                 :: "r"(d), "l"(src) : "memory");
}
#define CP_COMMIT() asm volatile("cp.async.commit_group;" ::: "memory")
#define CP_WAIT(n)  asm volatile("cp.async.wait_group %0;" :: "n"(n) : "memory")

// ---------------- kernel 1: build lists (CTA-aggregated) + zero out rows ---
// Counters arrive zeroed: statically on the first call, reset by the tail of
// the previous gemm launch on every later call.
__global__ __launch_bounds__(256) void build_kernel(
    const float* __restrict__ q_pts,   // [N,3]
    const float* __restrict__ s_pts,   // [M,3]
    const int*   __restrict__ inds,    // [N,32]
    const float* __restrict__ x,       // [M,64]  (fallback only)
    const float* __restrict__ W,       // [27,64,64] (fallback only)
    const float* __restrict__ kpts,    // [27,3]
    float* __restrict__ out,           // [N,64] (zeroed here)
    int N, int M)
{
    __shared__ unsigned eb_p[BCAP];
    __shared__ float    eb_w[BCAP];
    __shared__ unsigned char eb_k[BCAP];
    __shared__ int scnt[KK];
    __shared__ int soff[KK];
    __shared__ int stot;

    const int tid  = threadIdx.x;
    const int lane = tid & 31;
    const int gwarp = blockIdx.x * 8 + (tid >> 5);

    if (tid < KK) scnt[tid] = 0;
    if (tid == 0) stot = 0;
    __syncthreads();

    float kx = 0.f, ky = 0.f, kz = 0.f;
    if (lane < KK) {
        kx = kpts[lane * 3 + 0];
        ky = kpts[lane * 3 + 1];
        kz = kpts[lane * 3 + 2];
    }

    for (int q = gwarp; q < N; q += BCTAS * 8) {
        // zero this query's output row (warp owns q exclusively)
        *(float2*)(out + (size_t)q * CH + 2 * lane) = make_float2(0.f, 0.f);

        int ind = inds[q * 32 + lane];
        bool  alive = false;
        float dx = 0.f, dy = 0.f, dz = 0.f;
        if ((unsigned)ind < (unsigned)M) {
            float qx = q_pts[q * 3 + 0];
            float qy = q_pts[q * 3 + 1];
            float qz = q_pts[q * 3 + 2];
            dx = s_pts[ind * 3 + 0] - qx;
            dy = s_pts[ind * 3 + 1] - qy;
            dz = s_pts[ind * 3 + 2] - qz;
            alive = (dx * dx + dy * dy + dz * dz) < TH2;   // ~97% reject
        }

        unsigned mask = __ballot_sync(0xFFFFFFFFu, alive);
        while (mask) {
            int src = __ffs(mask) - 1;
            mask &= mask - 1;
            float sdx = __shfl_sync(0xFFFFFFFFu, dx, src);
            float sdy = __shfl_sync(0xFFFFFFFFu, dy, src);
            float sdz = __shfl_sync(0xFFFFFFFFu, dz, src);
            int   sind = __shfl_sync(0xFFFFFFFFu, ind, src);

            float ex = sdx - kx, ey = sdy - ky, ez = sdz - kz;
            float dd = ex * ex + ey * ey + ez * ez;
            if (lane < KK && dd < EXT2) {
                float w = 1.f - sqrtf(dd) * INV_EXT;
                int pos = atomicAdd(&stot, 1);
                if (pos < BCAP) {
                    eb_p[pos] = ((unsigned)q << 16) | (unsigned)sind;
                    eb_w[pos] = w;
                    eb_k[pos] = (unsigned char)lane;
                    atomicAdd(&scnt[lane], 1);
                } else {
                    // overflow fallback: direct global push (rare, correct)
                    int gp = atomicAdd(&g_cnt[lane * CNT_STRIDE], 1);
                    if (gp < CAPK) {
                        g_pack[lane * CAPK + gp] =
                            ((unsigned)q << 16) | (unsigned)sind;
                        g_w[lane * CAPK + gp] = w;
                    } else {
                        // capacity fallback (statistically unreachable)
                        const float* xr = x + (size_t)sind * CH;
                        const float* wk = W + (size_t)lane * CH * CH;
                        for (int o = 0; o < CH; o++) {
                            float a = 0.f;
                            for (int c = 0; c < CH; c++)
                                a += xr[c] * wk[c * CH + o];
                            atomicAdd(&out[(size_t)q * CH + o], w * a);
                        }
                    }
                }
            }
        }
    }
    __syncthreads();

    // ---- single flush: reserve per-k global ranges, scatter entries ----
    if (tid < KK)
        soff[tid] = atomicAdd(&g_cnt[tid * CNT_STRIDE], scnt[tid]);
    __syncthreads();
    int tot = min(stot, BCAP);
    for (int e = tid; e < tot; e += 256) {
        int kk = eb_k[e];
        int pos = atomicAdd(&soff[kk], 1);
        if (pos < CAPK) {
            g_pack[kk * CAPK + pos] = eb_p[e];
            g_w[kk * CAPK + pos]    = eb_w[e];
        } else {
            // capacity fallback (statistically unreachable)
            unsigned pk = eb_p[e];
            int sq = pk >> 16, si = pk & 0xFFFF;
            float w = eb_w[e];
            const float* xr = x + (size_t)si * CH;
            const float* wk = W + (size_t)kk * CH * CH;
            for (int o = 0; o < CH; o++) {
                float a = 0.f;
                for (int c = 0; c < CH; c++) a += xr[c] * wk[c * CH + o];
                atomicAdd(&out[(size_t)sq * CH + o], w * a);
            }
        }
    }
}

// ---------------- kernel 2: warp-decoupled per-k GEMM + scatter ------------
// grid (27, SLICES), 256 threads. Logical tile = 128 rows; warp wid owns rows
// [wid*16, wid*16+16) with a PRIVATE double-buffered smem slice + its own
// cp.async group FIFO. Exit protocol: every CTA increments g_done; the last
// one zeroes g_cnt for the next launch (replaces the zero kernel).
__global__ __launch_bounds__(256, 2) void gemm_kernel(
    const float* __restrict__ W,       // [27,64,64]
    const float* __restrict__ x,       // [M,64]
    float* __restrict__ out)           // [N,64]
{
    extern __shared__ float smem[];
    float* Ws  = smem;                             // 4096 floats
    float* xsW = Ws + CH * CH;                     // 8 * 2 * WROWS * PAD
    int*   qsW = (int*)(xsW + 8 * 2 * WROWS * PAD);   // 8 * 2 * WROWS
    float* swW = (float*)(qsW + 8 * 2 * WROWS);       // 8 * 2 * WROWS

    const int k    = blockIdx.x;
    const int tid  = threadIdx.x;
    const int wid  = tid >> 5;
    const int lane = tid & 31;
    const int rs   = lane >> 3;     // 0..3
    const int cg   = lane & 7;      // 0..7

    const int R = min(g_cnt[k * CNT_STRIDE], CAPK);
    const int ntiles = (R + 127) >> 7;
    const bool has_work = (R > 0) && ((int)blockIdx.y < ntiles);

    if (has_work) {
        int t = blockIdx.y;

        float* xw = xsW + wid * (2 * WROWS * PAD);
        int*   qw = qsW + wid * (2 * WROWS);
        float* ww = swW + wid * (2 * WROWS);

        {
            const float4* src = (const float4*)(W + (size_t)k * CH * CH);
            for (int i = tid; i < (CH * CH) / 4; i += 256)
                ((float4*)Ws)[i] = src[i];
        }

        auto fetch = [&](int tt, int p) {
            int base = (tt << 7) + wid * WROWS;
            float* dstb = xw + p * WROWS * PAD;
            #pragma unroll 4
            for (int i = 0; i < WROWS; i++) {
                int gi = base + i;
                unsigned pk = (gi < R) ? g_pack[k * CAPK + gi] : 0u;
                const float* src = x + (size_t)(pk & 0xFFFFu) * CH + 2 * lane;
                cp8(dstb + i * PAD + 2 * lane, src);
            }
            if (lane < WROWS) {
                int gi = base + lane;
                bool v = gi < R;
                unsigned pk = v ? g_pack[k * CAPK + gi] : 0u;
                qw[p * WROWS + lane] = (int)(pk >> 16);
                ww[p * WROWS + lane] = v ? g_w[k * CAPK + gi] : 0.f;
            }
            CP_COMMIT();
        };

        __syncthreads();                 // Ws visible to all warps
        fetch(t, 0);
        int pb = 0;

        for (; t < ntiles; t += SLICES) {
            int nxt = t + SLICES;
            bool hn = nxt < ntiles;
            if (hn) { fetch(nxt, pb ^ 1); CP_WAIT(1); }
            else    { CP_WAIT(0); }
            __syncwarp();

            const float* xb = xw + pb * WROWS * PAD;

            unsigned long long acc[4][4];
            #pragma unroll
            for (int a = 0; a < 4; a++)
                #pragma unroll
                for (int b = 0; b < 4; b++) acc[a][b] = 0ull;

            #pragma unroll 4
            for (int cin4 = 0; cin4 < 16; cin4++) {
                float4 xv0 = *(const float4*)&xb[(rs     ) * PAD + 4 * cin4];
                float4 xv1 = *(const float4*)&xb[(rs +  4) * PAD + 4 * cin4];
                float4 xv2 = *(const float4*)&xb[(rs +  8) * PAD + 4 * cin4];
                float4 xv3 = *(const float4*)&xb[(rs + 12) * PAD + 4 * cin4];
                const float* f0 = (const float*)&xv0;
                const float* f1 = (const float*)&xv1;
                const float* f2 = (const float*)&xv2;
                const float* f3 = (const float*)&xv3;
                #pragma unroll
                for (int j = 0; j < 4; j++) {
                    int cin = 4 * cin4 + j;
                    const ulonglong2* wp =
                        (const ulonglong2*)(Ws + cin * CH + 8 * cg);
                    ulonglong2 wv0 = wp[0];
                    ulonglong2 wv1 = wp[1];
                    unsigned long long px;
                    PACK2(px, f0[j], f0[j]);
                    FMA2(acc[0][0], px, wv0.x); FMA2(acc[0][1], px, wv0.y);
                    FMA2(acc[0][2], px, wv1.x); FMA2(acc[0][3], px, wv1.y);
                    PACK2(px, f1[j], f1[j]);
                    FMA2(acc[1][0], px, wv0.x); FMA2(acc[1][1], px, wv0.y);
                    FMA2(acc[1][2], px, wv1.x); FMA2(acc[1][3], px, wv1.y);
                    PACK2(px, f2[j], f2[j]);
                    FMA2(acc[2][0], px, wv0.x); FMA2(acc[2][1], px, wv0.y);
                    FMA2(acc[2][2], px, wv1.x); FMA2(acc[2][3], px, wv1.y);
                    PACK2(px, f3[j], f3[j]);
                    FMA2(acc[3][0], px, wv0.x); FMA2(acc[3][1], px, wv0.y);
                    FMA2(acc[3][2], px, wv1.x); FMA2(acc[3][3], px, wv1.y);
                }
            }

            int base = (t << 7) + wid * WROWS;
            #pragma unroll
            for (int rr = 0; rr < 4; rr++) {
                int row = rs + 4 * rr;
                if (base + row < R) {
                    float wt = ww[pb * WROWS + row];
                    float* op = out + (size_t)qw[pb * WROWS + row] * CH + 8 * cg;
                    unsigned a0, a1, a2, a3, b0, b1, b2, b3;
                    UNPACK2(a0, a1, acc[rr][0]);
                    UNPACK2(a2, a3, acc[rr][1]);
                    UNPACK2(b0, b1, acc[rr][2]);
                    UNPACK2(b2, b3, acc[rr][3]);
                    red_add_v4(op,
                               wt * __uint_as_float(a0), wt * __uint_as_float(a1),
                               wt * __uint_as_float(a2), wt * __uint_as_float(a3));
                    red_add_v4(op + 4,
                               wt * __uint_as_float(b0), wt * __uint_as_float(b1),
                               wt * __uint_as_float(b2), wt * __uint_as_float(b3));
                }
            }

            pb ^= 1;
            __syncwarp();
        }
        __syncthreads();   // all warps finished all g_pack/g_w/g_cnt reads
    }

    // ---- exit protocol: last CTA of the grid resets counters ----
    if (tid == 0) {
        __threadfence();
        if (atomicAdd(&g_done, 1) == KK * SLICES - 1) {
            #pragma unroll
            for (int kk = 0; kk < KK; kk++) g_cnt[kk * CNT_STRIDE] = 0;
            g_done = 0;
            __threadfence();
        }
    }
}

// ---------------- launcher --------------------------------------------------
extern "C" void kernel_launch(void* const* d_in, const int* in_sizes, int n_in,
                              void* d_out, int out_size) {
    const float* q_pts = (const float*)d_in[0];
    const float* s_pts = (const float*)d_in[1];
    const int*   inds  = (const int*)d_in[2];
    const float* x     = (const float*)d_in[3];
    const float* W     = (const float*)d_in[4];
    const float* kpts  = (const float*)d_in[5];
    float*       out   = (float*)d_out;

    int N = in_sizes[0] / 3;
    int M = in_sizes[1] / 3;

    // 1) CTA-aggregated build + out-row zeroing (counters pre-zeroed:
    //    statically on first call, by previous gemm tail afterwards)
    build_kernel<<<BCTAS, 256>>>(q_pts, s_pts, inds, x, W, kpts, out, N, M);

    // 2) warp-decoupled per-k GEMM + scatter (+ counter reset at exit)
    int smem = (CH * CH + 8 * 2 * WROWS * PAD) * 4
             + 8 * 2 * WROWS * 4 + 8 * 2 * WROWS * 4;   // 88064 B
    cudaFuncSetAttribute(gemm_kernel,
                         cudaFuncAttributeMaxDynamicSharedMemorySize, smem);
    dim3 grid(KK, SLICES);
    gemm_kernel<<<grid, 256, smem>>>(W, x, out);
}

// round 15
// speedup vs baseline: 1.4905x; 1.4905x over previous
#include <cuda_runtime.h>
#include <cstdint>

#define KK    27
#define CH    64
#define CAPK  65536          // per-k entry capacity (expected ~6K)
#define EXT2  0.75f          // KP_EXTENT^2
#define INV_EXT 1.15470053837925f
#define TH2   (1.8675f * 1.8675f)
#define SLICES 22
#define PAD   68             // floats per xs row (272B, 16B-aligned)
#define CNT_STRIDE 64        // 256B between counters -> distinct L2 slices
#define WROWS 16             // rows per warp per tile (8 warps x 16 = 128)
#define BCTAS 296            // build CTAs (grid-stride over queries)
#define BCAP  2048           // per-CTA entry staging capacity (expected ~510)

// global scratch (static __device__, zero-initialized at module load)
__device__ unsigned g_pack[KK * CAPK];   // q<<16 | ind
__device__ float    g_w[KK * CAPK];
__device__ int      g_cnt[KK * CNT_STRIDE];
__device__ int      g_done;              // gemm exit counter (self-resetting)

// ---------------- helpers ---------------------------------------------------
__device__ __forceinline__ void red_add_v2(float* p, float a, float b) {
    asm volatile("red.global.add.v2.f32 [%0], {%1, %2};"
                 :: "l"(p), "f"(a), "f"(b) : "memory");
}

__device__ __forceinline__ uint32_t f2tf32(float f) {
    uint32_t u;
    asm("cvt.rna.tf32.f32 %0, %1;" : "=r"(u) : "f"(f));
    return u;
}

__device__ __forceinline__ void mma_tf32(float* c, uint32_t a0, uint32_t a1,
                                         uint32_t a2, uint32_t a3,
                                         uint32_t b0, uint32_t b1) {
    asm volatile(
        "mma.sync.aligned.m16n8k8.row.col.f32.tf32.tf32.f32 "
        "{%0, %1, %2, %3}, {%4, %5, %6, %7}, {%8, %9}, {%0, %1, %2, %3};"
        : "+f"(c[0]), "+f"(c[1]), "+f"(c[2]), "+f"(c[3])
        : "r"(a0), "r"(a1), "r"(a2), "r"(a3), "r"(b0), "r"(b1));
}

__device__ __forceinline__ void cp8(float* dst_smem, const float* src) {
    unsigned d = (unsigned)__cvta_generic_to_shared(dst_smem);
    asm volatile("cp.async.ca.shared.global [%0], [%1], 8;"
                 :: "r"(d), "l"(src) : "memory");
}
#define CP_COMMIT() asm volatile("cp.async.commit_group;" ::: "memory")
#define CP_WAIT(n)  asm volatile("cp.async.wait_group %0;" :: "n"(n) : "memory")

// ---------------- kernel 1: build lists (CTA-aggregated) + zero out rows ---
__global__ __launch_bounds__(256) void build_kernel(
    const float* __restrict__ q_pts,   // [N,3]
    const float* __restrict__ s_pts,   // [M,3]
    const int*   __restrict__ inds,    // [N,32]
    const float* __restrict__ x,       // [M,64]  (fallback only)
    const float* __restrict__ W,       // [27,64,64] (fallback only)
    const float* __restrict__ kpts,    // [27,3]
    float* __restrict__ out,           // [N,64] (zeroed here)
    int N, int M)
{
    __shared__ unsigned eb_p[BCAP];
    __shared__ float    eb_w[BCAP];
    __shared__ unsigned char eb_k[BCAP];
    __shared__ int scnt[KK];
    __shared__ int soff[KK];
    __shared__ int stot;

    const int tid  = threadIdx.x;
    const int lane = tid & 31;
    const int gwarp = blockIdx.x * 8 + (tid >> 5);

    if (tid < KK) scnt[tid] = 0;
    if (tid == 0) stot = 0;
    __syncthreads();

    float kx = 0.f, ky = 0.f, kz = 0.f;
    if (lane < KK) {
        kx = kpts[lane * 3 + 0];
        ky = kpts[lane * 3 + 1];
        kz = kpts[lane * 3 + 2];
    }

    for (int q = gwarp; q < N; q += BCTAS * 8) {
        *(float2*)(out + (size_t)q * CH + 2 * lane) = make_float2(0.f, 0.f);

        int ind = inds[q * 32 + lane];
        bool  alive = false;
        float dx = 0.f, dy = 0.f, dz = 0.f;
        if ((unsigned)ind < (unsigned)M) {
            float qx = q_pts[q * 3 + 0];
            float qy = q_pts[q * 3 + 1];
            float qz = q_pts[q * 3 + 2];
            dx = s_pts[ind * 3 + 0] - qx;
            dy = s_pts[ind * 3 + 1] - qy;
            dz = s_pts[ind * 3 + 2] - qz;
            alive = (dx * dx + dy * dy + dz * dz) < TH2;   // ~97% reject
        }

        unsigned mask = __ballot_sync(0xFFFFFFFFu, alive);
        while (mask) {
            int src = __ffs(mask) - 1;
            mask &= mask - 1;
            float sdx = __shfl_sync(0xFFFFFFFFu, dx, src);
            float sdy = __shfl_sync(0xFFFFFFFFu, dy, src);
            float sdz = __shfl_sync(0xFFFFFFFFu, dz, src);
            int   sind = __shfl_sync(0xFFFFFFFFu, ind, src);

            float ex = sdx - kx, ey = sdy - ky, ez = sdz - kz;
            float dd = ex * ex + ey * ey + ez * ez;
            if (lane < KK && dd < EXT2) {
                float w = 1.f - sqrtf(dd) * INV_EXT;
                int pos = atomicAdd(&stot, 1);
                if (pos < BCAP) {
                    eb_p[pos] = ((unsigned)q << 16) | (unsigned)sind;
                    eb_w[pos] = w;
                    eb_k[pos] = (unsigned char)lane;
                    atomicAdd(&scnt[lane], 1);
                } else {
                    // overflow fallback: direct global push (rare, correct)
                    int gp = atomicAdd(&g_cnt[lane * CNT_STRIDE], 1);
                    if (gp < CAPK) {
                        g_pack[lane * CAPK + gp] =
                            ((unsigned)q << 16) | (unsigned)sind;
                        g_w[lane * CAPK + gp] = w;
                    } else {
                        // capacity fallback (statistically unreachable)
                        const float* xr = x + (size_t)sind * CH;
                        const float* wk = W + (size_t)lane * CH * CH;
                        for (int o = 0; o < CH; o++) {
                            float a = 0.f;
                            for (int c = 0; c < CH; c++)
                                a += xr[c] * wk[c * CH + o];
                            atomicAdd(&out[(size_t)q * CH + o], w * a);
                        }
                    }
                }
            }
        }
    }
    __syncthreads();

    // ---- single flush: reserve per-k global ranges, scatter entries ----
    if (tid < KK)
        soff[tid] = atomicAdd(&g_cnt[tid * CNT_STRIDE], scnt[tid]);
    __syncthreads();
    int tot = min(stot, BCAP);
    for (int e = tid; e < tot; e += 256) {
        int kk = eb_k[e];
        int pos = atomicAdd(&soff[kk], 1);
        if (pos < CAPK) {
            g_pack[kk * CAPK + pos] = eb_p[e];
            g_w[kk * CAPK + pos]    = eb_w[e];
        } else {
            // capacity fallback (statistically unreachable)
            unsigned pk = eb_p[e];
            int sq = pk >> 16, si = pk & 0xFFFF;
            float w = eb_w[e];
            const float* xr = x + (size_t)si * CH;
            const float* wk = W + (size_t)kk * CH * CH;
            for (int o = 0; o < CH; o++) {
                float a = 0.f;
                for (int c = 0; c < CH; c++) a += xr[c] * wk[c * CH + o];
                atomicAdd(&out[(size_t)sq * CH + o], w * a);
            }
        }
    }
}

// ---------------- kernel 2: warp-decoupled tf32 mma GEMM + scatter ---------
// grid (27, SLICES), 256 threads. Logical tile = 128 rows; warp wid owns rows
// [wid*16, wid*16+16) with a PRIVATE double-buffered smem slice + its own
// cp.async FIFO. Mainloop = mma.sync.m16n8k8 tf32 (2 m-tiles x 8 n-tiles per
// warp per 16x64x64 slab). W is pre-baked per CTA into fragment order.
// Exit protocol: last CTA of grid zeroes g_cnt for the next launch.
__global__ __launch_bounds__(256, 2) void gemm_kernel(
    const float* __restrict__ W,       // [27,64,64]
    const float* __restrict__ x,       // [M,64]
    float* __restrict__ out)           // [N,64]
{
    extern __shared__ float smem[];
    float* Bf  = smem;                             // 64 tiles * 64 = 4096 f
    float* xsW = Bf + 4096;                        // 8 * 2 * WROWS * PAD
    int*   qsW = (int*)(xsW + 8 * 2 * WROWS * PAD);   // 8 * 2 * WROWS
    float* swW = (float*)(qsW + 8 * 2 * WROWS);       // 8 * 2 * WROWS

    const int k    = blockIdx.x;
    const int tid  = threadIdx.x;
    const int wid  = tid >> 5;
    const int lane = tid & 31;
    const int gid  = lane >> 2;     // groupID 0..7
    const int tig  = lane & 3;      // thread-in-group 0..3

    const int R = min(g_cnt[k * CNT_STRIDE], CAPK);
    const int ntiles = (R + 127) >> 7;
    const bool has_work = (R > 0) && ((int)blockIdx.y < ntiles);

    if (has_work) {
        int t = blockIdx.y;

        float* xw = xsW + wid * (2 * WROWS * PAD);
        int*   qw = qsW + wid * (2 * WROWS);
        float* ww = swW + wid * (2 * WROWS);

        // ---- pre-bake W[k] into mma B-fragment order (once per CTA) ----
        // Fragment for (ktile kt, ntile nt): b0 = W[kt*8+tig][nt*8+gid],
        // b1 = W[kt*8+tig+4][nt*8+gid]; stored at Bf[(kt*8+nt)*64 + lane*2].
        {
            const float* Wk = W + (size_t)k * CH * CH;
            #pragma unroll
            for (int j = 0; j < 8; j++) {
                int tt = wid * 8 + j;          // 0..63
                int kt = tt >> 3, nt = tt & 7;
                float b0 = Wk[(kt * 8 + tig) * CH + nt * 8 + gid];
                float b1 = Wk[(kt * 8 + tig + 4) * CH + nt * 8 + gid];
                uint32_t u0 = f2tf32(b0), u1 = f2tf32(b1);
                *(uint2*)&Bf[tt * 64 + lane * 2] = make_uint2(u0, u1);
            }
        }

        auto fetch = [&](int tt, int p) {
            int base = (tt << 7) + wid * WROWS;
            float* dstb = xw + p * WROWS * PAD;
            #pragma unroll 4
            for (int i = 0; i < WROWS; i++) {
                int gi = base + i;
                unsigned pk = (gi < R) ? g_pack[k * CAPK + gi] : 0u;
                const float* src = x + (size_t)(pk & 0xFFFFu) * CH + 2 * lane;
                cp8(dstb + i * PAD + 2 * lane, src);
            }
            if (lane < WROWS) {
                int gi = base + lane;
                bool v = gi < R;
                unsigned pk = v ? g_pack[k * CAPK + gi] : 0u;
                qw[p * WROWS + lane] = (int)(pk >> 16);
                ww[p * WROWS + lane] = v ? g_w[k * CAPK + gi] : 0.f;
            }
            CP_COMMIT();
        };

        __syncthreads();                 // Bf visible to all warps
        fetch(t, 0);
        int pb = 0;

        for (; t < ntiles; t += SLICES) {
            int nxt = t + SLICES;
            bool hn = nxt < ntiles;
            if (hn) { fetch(nxt, pb ^ 1); CP_WAIT(1); }
            else    { CP_WAIT(0); }
            __syncwarp();

            const float* xb = xw + pb * WROWS * PAD;

            float acc[8][4];
            #pragma unroll
            for (int n = 0; n < 8; n++)
                #pragma unroll
                for (int j = 0; j < 4; j++) acc[n][j] = 0.f;

            #pragma unroll
            for (int ks = 0; ks < 8; ks++) {
                // A fragments (conflict-free: stride 68 = 4 mod 32)
                int c0 = ks * 8 + tig;
                uint32_t a0 = f2tf32(xb[gid * PAD + c0]);
                uint32_t a1 = f2tf32(xb[(gid + 8) * PAD + c0]);
                uint32_t a2 = f2tf32(xb[gid * PAD + c0 + 4]);
                uint32_t a3 = f2tf32(xb[(gid + 8) * PAD + c0 + 4]);
                const uint2* bp = (const uint2*)&Bf[(ks * 8) * 64 + lane * 2];
                #pragma unroll
                for (int n = 0; n < 8; n++) {
                    uint2 bv = bp[n * 32];     // LDS.64, conflict-free
                    mma_tf32(acc[n], a0, a1, a2, a3, bv.x, bv.y);
                }
            }

            // epilogue: wt-scale + v2 global reductions
            {
                int base = (t << 7) + wid * WROWS;
                bool v0 = (base + gid) < R;
                bool v1 = (base + gid + 8) < R;
                float wt0 = v0 ? ww[pb * WROWS + gid] : 0.f;
                float wt1 = v1 ? ww[pb * WROWS + gid + 8] : 0.f;
                float* o0 = v0 ? out + (size_t)qw[pb * WROWS + gid] * CH
                                     + 2 * tig
                               : 0;
                float* o1 = v1 ? out + (size_t)qw[pb * WROWS + gid + 8] * CH
                                     + 2 * tig
                               : 0;
                #pragma unroll
                for (int n = 0; n < 8; n++) {
                    if (v0) red_add_v2(o0 + n * 8,
                                       wt0 * acc[n][0], wt0 * acc[n][1]);
                    if (v1) red_add_v2(o1 + n * 8,
                                       wt1 * acc[n][2], wt1 * acc[n][3]);
                }
            }

            pb ^= 1;
            __syncwarp();
        }
    }

    // ---- exit protocol: last CTA of the grid resets counters ----
    if (tid == 0) {
        __threadfence();
        if (atomicAdd(&g_done, 1) == KK * SLICES - 1) {
            #pragma unroll
            for (int kk = 0; kk < KK; kk++) g_cnt[kk * CNT_STRIDE] = 0;
            g_done = 0;
            __threadfence();
        }
    }
}

// ---------------- launcher --------------------------------------------------
extern "C" void kernel_launch(void* const* d_in, const int* in_sizes, int n_in,
                              void* d_out, int out_size) {
    const float* q_pts = (const float*)d_in[0];
    const float* s_pts = (const float*)d_in[1];
    const int*   inds  = (const int*)d_in[2];
    const float* x     = (const float*)d_in[3];
    const float* W     = (const float*)d_in[4];
    const float* kpts  = (const float*)d_in[5];
    float*       out   = (float*)d_out;

    int N = in_sizes[0] / 3;
    int M = in_sizes[1] / 3;

    // 1) CTA-aggregated build + out-row zeroing (counters pre-zeroed:
    //    statically on first call, by previous gemm tail afterwards)
    build_kernel<<<BCTAS, 256>>>(q_pts, s_pts, inds, x, W, kpts, out, N, M);

    // 2) warp-decoupled tf32 mma GEMM + scatter (+ counter reset at exit)
    int smem = (4096 + 8 * 2 * WROWS * PAD) * 4
             + 8 * 2 * WROWS * 4 + 8 * 2 * WROWS * 4;   // 88064 B
    cudaFuncSetAttribute(gemm_kernel,
                         cudaFuncAttributeMaxDynamicSharedMemorySize, smem);
    dim3 grid(KK, SLICES);
    gemm_kernel<<<grid, 256, smem>>>(W, x, out);
}